// round 2
// baseline (speedup 1.0000x reference)
#include <cuda_runtime.h>

#define N_NODES 100000
#define N_EDGES 640000
#define D 128
#define NL 3

// ---- scratch (device globals: no allocation allowed in kernel_launch) ----
__device__ float g_h[(size_t)N_NODES * D];     // per-layer GEMM output
__device__ float g_bufA[(size_t)N_NODES * D];  // layer ping
__device__ float g_bufB[(size_t)N_NODES * D];  // layer pong
__device__ float g_deg[N_NODES];
__device__ float g_dinv[N_NODES];
__device__ float g_norm[N_EDGES];
__device__ int   g_ei[2 * N_EDGES];            // normalized int32 edge index

// ---------------- edge-index dtype sniff + convert ----------------
// JAX with x64 disabled silently makes "int64" edge_index int32. Detect by
// inspecting the first 16 odd int32 words: for little-endian int64 values in
// [0, 100000) they are all zero; for int32 data they are random node ids.
__device__ __forceinline__ bool ei_is_int64(const int* __restrict__ w) {
    bool z = true;
#pragma unroll
    for (int i = 1; i < 32; i += 2) z &= (w[i] == 0);
    return z;
}

__global__ void k_convert(const int* __restrict__ ei_raw, int* __restrict__ ei32) {
    int i = blockIdx.x * blockDim.x + threadIdx.x;
    if (i >= 2 * N_EDGES) return;
    bool is64 = ei_is_int64(ei_raw);
    ei32[i] = is64 ? ei_raw[2 * i] : ei_raw[i];
}

// ---------------- prep kernels ----------------
__global__ void k_zero(float* __restrict__ p, int n) {
    int i = blockIdx.x * blockDim.x + threadIdx.x;
    if (i < n) p[i] = 0.f;
}

__global__ void k_deg(const int* __restrict__ ei, float* __restrict__ deg) {
    int e = blockIdx.x * blockDim.x + threadIdx.x;
    if (e < N_EDGES) {
        int c = ei[N_EDGES + e];  // target
        atomicAdd(&deg[c], 1.0f);
    }
}

__global__ void k_dinv(const float* __restrict__ deg, float* __restrict__ dinv) {
    int i = blockIdx.x * blockDim.x + threadIdx.x;
    if (i < N_NODES) {
        float d = deg[i];
        dinv[i] = (d > 0.f) ? rsqrtf(d) : 0.f;
    }
}

__global__ void k_norm(const int* __restrict__ ei, const float* __restrict__ dinv,
                       float* __restrict__ norm) {
    int e = blockIdx.x * blockDim.x + threadIdx.x;
    if (e < N_EDGES) {
        int r = ei[e];
        int c = ei[N_EDGES + e];
        norm[e] = dinv[r] * dinv[c];
    }
}

// ---------------- bias broadcast init: out[n][c] = b[c] ----------------
__global__ void k_bias(float* __restrict__ out, const float* __restrict__ b) {
    int i = blockIdx.x * blockDim.x + threadIdx.x;  // float4 index
    const int total = N_NODES * D / 4;
    if (i < total) {
        float4 bv = ((const float4*)b)[i & (D / 4 - 1)];
        ((float4*)out)[i] = bv;
    }
}

// ---------------- GEMM: H[N,128] = act(X[N,128]) @ Wm[128,128] ----------------
// Block = 256 threads, 16 rows per block. K tiled by 64 (36 KB static smem).
// thread t: c = t & 127 (output column), rg = t >> 7 (row half), 8 rows each.
template <bool RELU>
__global__ __launch_bounds__(256) void k_gemm(const float* __restrict__ X,
                                              const float* __restrict__ Wm,
                                              float* __restrict__ H) {
    __shared__ float Ws[64 * 128];  // 32 KB
    __shared__ float xs[16 * 64];   // 4 KB

    const int t = threadIdx.x;
    const int c = t & 127;
    const int rg = t >> 7;
    const int row0 = blockIdx.x * 16;

    float acc[8];
#pragma unroll
    for (int j = 0; j < 8; j++) acc[j] = 0.f;

    for (int kt = 0; kt < 128; kt += 64) {
        // load W tile: 64x128 floats = 2048 float4, 8 per thread, coalesced
        const float4* wsrc = (const float4*)(Wm + kt * 128);
        float4* wdst = (float4*)Ws;
#pragma unroll
        for (int j = 0; j < 8; j++) wdst[t + j * 256] = wsrc[t + j * 256];

        // load X tile: 16 rows x 64 k = 256 float4, 1 per thread
        {
            int r = t >> 4;       // 16 float4 per row
            int k4 = t & 15;
            float4 xv = *(const float4*)(X + (long long)(row0 + r) * D + kt + k4 * 4);
            if (RELU) {
                xv.x = fmaxf(xv.x, 0.f);
                xv.y = fmaxf(xv.y, 0.f);
                xv.z = fmaxf(xv.z, 0.f);
                xv.w = fmaxf(xv.w, 0.f);
            }
            *(float4*)&xs[r * 64 + k4 * 4] = xv;
        }
        __syncthreads();

#pragma unroll
        for (int kk = 0; kk < 64; kk += 4) {
            float w0 = Ws[(kk + 0) * 128 + c];
            float w1 = Ws[(kk + 1) * 128 + c];
            float w2 = Ws[(kk + 2) * 128 + c];
            float w3 = Ws[(kk + 3) * 128 + c];
#pragma unroll
            for (int j = 0; j < 8; j++) {
                float4 xv = *(const float4*)&xs[(rg * 8 + j) * 64 + kk];
                acc[j] = fmaf(xv.x, w0, acc[j]);
                acc[j] = fmaf(xv.y, w1, acc[j]);
                acc[j] = fmaf(xv.z, w2, acc[j]);
                acc[j] = fmaf(xv.w, w3, acc[j]);
            }
        }
        __syncthreads();
    }

#pragma unroll
    for (int j = 0; j < 8; j++)
        H[(long long)(row0 + rg * 8 + j) * D + c] = acc[j];
}

// ---------------- edge scatter: out[col] += h[row] * norm[e] ----------------
// One warp per edge: lane l handles dims [4l, 4l+4). Coalesced 512B gather,
// vector red.global.add.v4.f32 reduction (4x fewer atomic instrs than scalar).
__global__ __launch_bounds__(256) void k_scatter(const int* __restrict__ ei,
                                                 const float* __restrict__ norm,
                                                 const float* __restrict__ H,
                                                 float* __restrict__ out) {
    int e = blockIdx.x * 8 + (threadIdx.x >> 5);
    if (e >= N_EDGES) return;
    int lane = threadIdx.x & 31;

    int r = ei[e];
    int c = ei[N_EDGES + e];
    float nv = norm[e];

    float4 v = ((const float4*)(H + (long long)r * D))[lane];
    v.x *= nv; v.y *= nv; v.z *= nv; v.w *= nv;

    float* dst = out + (long long)c * D + lane * 4;
    asm volatile("red.global.add.v4.f32 [%0], {%1,%2,%3,%4};"
                 :: "l"(dst), "f"(v.x), "f"(v.y), "f"(v.z), "f"(v.w)
                 : "memory");
}

// ---------------- launch ----------------
extern "C" void kernel_launch(void* const* d_in, const int* in_sizes, int n_in,
                              void* d_out, int out_size) {
    const float* x = (const float*)d_in[0];
    const int* ei_raw = (const int*)d_in[1];
    // d_in[2] = batch (unused)
    const float* W = (const float*)d_in[3];
    const float* b = (const float*)d_in[4];
    float* out = (float*)d_out;

    float *deg, *dinv, *norm, *h, *bufA, *bufB;
    int* ei;
    cudaGetSymbolAddress((void**)&deg, g_deg);
    cudaGetSymbolAddress((void**)&dinv, g_dinv);
    cudaGetSymbolAddress((void**)&norm, g_norm);
    cudaGetSymbolAddress((void**)&h, g_h);
    cudaGetSymbolAddress((void**)&bufA, g_bufA);
    cudaGetSymbolAddress((void**)&bufB, g_bufB);
    cudaGetSymbolAddress((void**)&ei, g_ei);

    const int TPB = 256;

    // normalize edge index dtype (int64 or int32) into int32 scratch
    k_convert<<<(2 * N_EDGES + TPB - 1) / TPB, TPB>>>(ei_raw, ei);

    // norm precompute
    k_zero<<<(N_NODES + TPB - 1) / TPB, TPB>>>(deg, N_NODES);
    k_deg<<<(N_EDGES + TPB - 1) / TPB, TPB>>>(ei, deg);
    k_dinv<<<(N_NODES + TPB - 1) / TPB, TPB>>>(deg, dinv);
    k_norm<<<(N_EDGES + TPB - 1) / TPB, TPB>>>(ei, dinv, norm);

    const int GEMM_BLOCKS = N_NODES / 16;              // 6250 (exact)
    const int BIAS_BLOCKS = (N_NODES * D / 4 + TPB - 1) / TPB;
    const int SCAT_BLOCKS = (N_EDGES + 7) / 8;

    // layer 0: x -> bufA
    k_gemm<false><<<GEMM_BLOCKS, TPB>>>(x, W + 0 * D * D, h);
    k_bias<<<BIAS_BLOCKS, TPB>>>(bufA, b + 0 * D);
    k_scatter<<<SCAT_BLOCKS, TPB>>>(ei, norm, h, bufA);

    // layer 1: relu(bufA) -> bufB
    k_gemm<true><<<GEMM_BLOCKS, TPB>>>(bufA, W + 1 * D * D, h);
    k_bias<<<BIAS_BLOCKS, TPB>>>(bufB, b + 1 * D);
    k_scatter<<<SCAT_BLOCKS, TPB>>>(ei, norm, h, bufB);

    // layer 2: relu(bufB) -> d_out (no final relu)
    k_gemm<true><<<GEMM_BLOCKS, TPB>>>(bufB, W + 2 * D * D, h);
    k_bias<<<BIAS_BLOCKS, TPB>>>(out, b + 2 * D);
    k_scatter<<<SCAT_BLOCKS, TPB>>>(ei, norm, h, out);
}

// round 3
// speedup vs baseline: 1.4195x; 1.4195x over previous
#include <cuda_runtime.h>

#define N_NODES 100000
#define N_EDGES 640000
#define D 128
#define SCAN_BS 1024
#define N_SCAN_BLOCKS ((N_NODES + SCAN_BS - 1) / SCAN_BS)  // 98

// ---- scratch (device globals: no allocation allowed) ----
__device__ float g_h[(size_t)N_NODES * D];
__device__ float g_bufA[(size_t)N_NODES * D];
__device__ float g_bufB[(size_t)N_NODES * D];
__device__ int   g_deg[N_NODES];
__device__ float g_dinv[N_NODES];
__device__ int   g_rowptr[N_NODES + 1];
__device__ int   g_cursor[N_NODES];
__device__ int   g_bsum[128];
__device__ int   g_boff[128];
__device__ int   g_esrc[N_EDGES];
__device__ float g_enorm[N_EDGES];
__device__ int   g_ei[2 * N_EDGES];

// ---------------- edge-index dtype sniff + convert ----------------
__device__ __forceinline__ bool ei_is_int64(const int* __restrict__ w) {
    bool z = true;
#pragma unroll
    for (int i = 1; i < 32; i += 2) z &= (w[i] == 0);
    return z;
}

__global__ void k_convert(const int* __restrict__ ei_raw, int* __restrict__ ei32) {
    int i = blockIdx.x * blockDim.x + threadIdx.x;
    if (i >= 2 * N_EDGES) return;
    bool is64 = ei_is_int64(ei_raw);
    ei32[i] = is64 ? ei_raw[2 * i] : ei_raw[i];
}

// ---------------- degree / norm prep ----------------
__global__ void k_zeroi(int* __restrict__ p, int n) {
    int i = blockIdx.x * blockDim.x + threadIdx.x;
    if (i < n) p[i] = 0;
}

__global__ void k_hist(const int* __restrict__ ei, int* __restrict__ deg) {
    int e = blockIdx.x * blockDim.x + threadIdx.x;
    if (e < N_EDGES) atomicAdd(&deg[ei[N_EDGES + e]], 1);
}

__global__ void k_dinv(const int* __restrict__ deg, float* __restrict__ dinv) {
    int i = blockIdx.x * blockDim.x + threadIdx.x;
    if (i < N_NODES) {
        int d = deg[i];
        dinv[i] = (d > 0) ? rsqrtf((float)d) : 0.f;
    }
}

// ---------------- exclusive scan of deg -> rowptr (+cursor copy) ----------------
__global__ __launch_bounds__(256) void k_blocksum(const int* __restrict__ deg, int* __restrict__ bsum) {
    __shared__ int s[256];
    int b = blockIdx.x, t = threadIdx.x;
    int base = b * SCAN_BS + t * 4;
    int v = 0;
#pragma unroll
    for (int j = 0; j < 4; j++) {
        int i = base + j;
        if (i < N_NODES) v += deg[i];
    }
    s[t] = v;
    __syncthreads();
    for (int off = 128; off > 0; off >>= 1) {
        if (t < off) s[t] += s[t + off];
        __syncthreads();
    }
    if (t == 0) bsum[b] = s[0];
}

__global__ __launch_bounds__(128) void k_scansums(const int* __restrict__ bsum,
                                                  int* __restrict__ boff,
                                                  int* __restrict__ rowptr) {
    __shared__ int s[128];
    int t = threadIdx.x;
    int v = (t < N_SCAN_BLOCKS) ? bsum[t] : 0;
    s[t] = v;
    __syncthreads();
    for (int off = 1; off < 128; off <<= 1) {
        int u = (t >= off) ? s[t - off] : 0;
        __syncthreads();
        s[t] += u;
        __syncthreads();
    }
    if (t < N_SCAN_BLOCKS) boff[t] = s[t] - v;  // exclusive
    if (t == N_SCAN_BLOCKS - 1) rowptr[N_NODES] = s[t];
}

__global__ __launch_bounds__(SCAN_BS) void k_scanapply(const int* __restrict__ deg,
                                                       const int* __restrict__ boff,
                                                       int* __restrict__ rowptr,
                                                       int* __restrict__ cursor) {
    __shared__ int s[SCAN_BS];
    int b = blockIdx.x, t = threadIdx.x;
    int i = b * SCAN_BS + t;
    int v = (i < N_NODES) ? deg[i] : 0;
    s[t] = v;
    __syncthreads();
    for (int off = 1; off < SCAN_BS; off <<= 1) {
        int u = (t >= off) ? s[t - off] : 0;
        __syncthreads();
        s[t] += u;
        __syncthreads();
    }
    if (i < N_NODES) {
        int excl = boff[b] + s[t] - v;
        rowptr[i] = excl;
        cursor[i] = excl;
    }
}

// ---------------- bucket edges by target ----------------
__global__ void k_fill(const int* __restrict__ ei, const float* __restrict__ dinv,
                       int* __restrict__ cursor, int* __restrict__ esrc,
                       float* __restrict__ enorm) {
    int e = blockIdx.x * blockDim.x + threadIdx.x;
    if (e >= N_EDGES) return;
    int r = ei[e];
    int c = ei[N_EDGES + e];
    int pos = atomicAdd(&cursor[c], 1);
    esrc[pos] = r;
    enorm[pos] = dinv[r] * dinv[c];
}

// ---------------- f32x2 GEMM: H = act(X) @ W ----------------
// Block: 32 rows x 128 cols, 256 threads. Dynamic smem: full W (64KB, row-major
// w[k][c]) + duplicated-transposed X tile xs2[k][2r]={x,x} (pad 66, 33KB).
// Thread t: cq = t&31 -> cols 4cq..4cq+3 (2 f32x2 col-pairs, aliased from W
// register pairs); rg = t>>5 -> rows 4rg..4rg+3. 8 fma.rn.f32x2 per k.
#define XS2_STRIDE 66
#define GEMM_SMEM (128 * 128 * 4 + 128 * XS2_STRIDE * 4)

__device__ __forceinline__ void ffma2(unsigned long long& d, unsigned long long a,
                                      unsigned long long b) {
    asm("fma.rn.f32x2 %0, %1, %2, %0;" : "+l"(d) : "l"(a), "l"(b));
}

template <bool RELU>
__global__ __launch_bounds__(256) void k_gemm(const float* __restrict__ X,
                                              const float* __restrict__ Wm,
                                              float* __restrict__ H) {
    extern __shared__ float smem[];
    float* Ws = smem;                 // 128*128
    float* xs2 = smem + 128 * 128;    // 128*66

    const int t = threadIdx.x;
    const int cq = t & 31;
    const int rg = t >> 5;
    const int row0 = blockIdx.x * 32;

    // load W (64KB): 4096 float4, 16 per thread, coalesced
    {
        const float4* wsrc = (const float4*)Wm;
        float4* wdst = (float4*)Ws;
#pragma unroll
        for (int j = 0; j < 16; j++) wdst[t + j * 256] = wsrc[t + j * 256];
    }
    // load X tile (32 rows x 128) -> duplicated transpose xs2[k][2r]={v,v}
    {
        int r = t >> 3;        // 0..31
        int q = t & 7;
#pragma unroll
        for (int j = 0; j < 4; j++) {
            int f = q + j * 8;  // float4 col index 0..31
            float4 v = ((const float4*)(X + (size_t)(row0 + r) * D))[f];
            if (RELU) {
                v.x = fmaxf(v.x, 0.f); v.y = fmaxf(v.y, 0.f);
                v.z = fmaxf(v.z, 0.f); v.w = fmaxf(v.w, 0.f);
            }
            int k = f * 4;
            *(float2*)&xs2[(k + 0) * XS2_STRIDE + 2 * r] = make_float2(v.x, v.x);
            *(float2*)&xs2[(k + 1) * XS2_STRIDE + 2 * r] = make_float2(v.y, v.y);
            *(float2*)&xs2[(k + 2) * XS2_STRIDE + 2 * r] = make_float2(v.z, v.z);
            *(float2*)&xs2[(k + 3) * XS2_STRIDE + 2 * r] = make_float2(v.w, v.w);
        }
    }
    __syncthreads();

    unsigned long long acc[4][2];
#pragma unroll
    for (int j = 0; j < 4; j++) { acc[j][0] = 0ull; acc[j][1] = 0ull; }

#pragma unroll 8
    for (int k = 0; k < 128; k++) {
        unsigned long long wlo = *(const unsigned long long*)(Ws + k * 128 + cq * 4);
        unsigned long long whi = *(const unsigned long long*)(Ws + k * 128 + cq * 4 + 2);
        const float* xb = xs2 + k * XS2_STRIDE + rg * 8;
        unsigned long long a0 = *(const unsigned long long*)(xb + 0);
        unsigned long long a1 = *(const unsigned long long*)(xb + 2);
        unsigned long long a2 = *(const unsigned long long*)(xb + 4);
        unsigned long long a3 = *(const unsigned long long*)(xb + 6);
        ffma2(acc[0][0], a0, wlo); ffma2(acc[0][1], a0, whi);
        ffma2(acc[1][0], a1, wlo); ffma2(acc[1][1], a1, whi);
        ffma2(acc[2][0], a2, wlo); ffma2(acc[2][1], a2, whi);
        ffma2(acc[3][0], a3, wlo); ffma2(acc[3][1], a3, whi);
    }

#pragma unroll
    for (int j = 0; j < 4; j++) {
        float2 lo = *(float2*)&acc[j][0];
        float2 hi = *(float2*)&acc[j][1];
        float4 o = make_float4(lo.x, lo.y, hi.x, hi.y);
        ((float4*)(H + (size_t)(row0 + rg * 4 + j) * D))[cq] = o;
    }
}

// ---------------- CSR gather: out[n] = b + sum_{e in row n} h[esrc[e]]*enorm[e] ----------------
__global__ __launch_bounds__(256) void k_gather(const int* __restrict__ rowptr,
                                                const int* __restrict__ esrc,
                                                const float* __restrict__ enorm,
                                                const float* __restrict__ H,
                                                const float* __restrict__ bvec,
                                                float* __restrict__ out) {
    int n = blockIdx.x * 8 + (threadIdx.x >> 5);
    if (n >= N_NODES) return;
    int lane = threadIdx.x & 31;

    float4 bv = ((const float4*)bvec)[lane];
    float4 acc = bv;

    int e = rowptr[n];
    int end = rowptr[n + 1];
    for (; e + 2 <= end; e += 2) {
        int s0 = esrc[e], s1 = esrc[e + 1];
        float n0 = enorm[e], n1 = enorm[e + 1];
        float4 v0 = ((const float4*)(H + (size_t)s0 * D))[lane];
        float4 v1 = ((const float4*)(H + (size_t)s1 * D))[lane];
        acc.x += v0.x * n0 + v1.x * n1;
        acc.y += v0.y * n0 + v1.y * n1;
        acc.z += v0.z * n0 + v1.z * n1;
        acc.w += v0.w * n0 + v1.w * n1;
    }
    if (e < end) {
        int s0 = esrc[e];
        float n0 = enorm[e];
        float4 v0 = ((const float4*)(H + (size_t)s0 * D))[lane];
        acc.x += v0.x * n0; acc.y += v0.y * n0;
        acc.z += v0.z * n0; acc.w += v0.w * n0;
    }
    ((float4*)(out + (size_t)n * D))[lane] = acc;
}

// ---------------- launch ----------------
extern "C" void kernel_launch(void* const* d_in, const int* in_sizes, int n_in,
                              void* d_out, int out_size) {
    const float* x = (const float*)d_in[0];
    const int* ei_raw = (const int*)d_in[1];
    const float* W = (const float*)d_in[3];
    const float* b = (const float*)d_in[4];
    float* out = (float*)d_out;

    float *dinv, *h, *bufA, *bufB, *enorm;
    int *deg, *rowptr, *cursor, *bsum, *boff, *esrc, *ei;
    cudaGetSymbolAddress((void**)&dinv, g_dinv);
    cudaGetSymbolAddress((void**)&h, g_h);
    cudaGetSymbolAddress((void**)&bufA, g_bufA);
    cudaGetSymbolAddress((void**)&bufB, g_bufB);
    cudaGetSymbolAddress((void**)&enorm, g_enorm);
    cudaGetSymbolAddress((void**)&deg, g_deg);
    cudaGetSymbolAddress((void**)&rowptr, g_rowptr);
    cudaGetSymbolAddress((void**)&cursor, g_cursor);
    cudaGetSymbolAddress((void**)&bsum, g_bsum);
    cudaGetSymbolAddress((void**)&boff, g_boff);
    cudaGetSymbolAddress((void**)&esrc, g_esrc);
    cudaGetSymbolAddress((void**)&ei, g_ei);

    cudaFuncSetAttribute(k_gemm<false>, cudaFuncAttributeMaxDynamicSharedMemorySize, GEMM_SMEM);
    cudaFuncSetAttribute(k_gemm<true>, cudaFuncAttributeMaxDynamicSharedMemorySize, GEMM_SMEM);

    const int TPB = 256;

    // prep: normalize indices, degree, dinv, CSR build
    k_convert<<<(2 * N_EDGES + TPB - 1) / TPB, TPB>>>(ei_raw, ei);
    k_zeroi<<<(N_NODES + TPB - 1) / TPB, TPB>>>(deg, N_NODES);
    k_hist<<<(N_EDGES + TPB - 1) / TPB, TPB>>>(ei, deg);
    k_dinv<<<(N_NODES + TPB - 1) / TPB, TPB>>>(deg, dinv);
    k_blocksum<<<N_SCAN_BLOCKS, 256>>>(deg, bsum);
    k_scansums<<<1, 128>>>(bsum, boff, rowptr);
    k_scanapply<<<N_SCAN_BLOCKS, SCAN_BS>>>(deg, boff, rowptr, cursor);
    k_fill<<<(N_EDGES + TPB - 1) / TPB, TPB>>>(ei, dinv, cursor, esrc, enorm);

    const int GEMM_BLOCKS = N_NODES / 32;      // 3125 exact
    const int GATH_BLOCKS = (N_NODES + 7) / 8;

    // layer 0
    k_gemm<false><<<GEMM_BLOCKS, TPB, GEMM_SMEM>>>(x, W + 0 * D * D, h);
    k_gather<<<GATH_BLOCKS, TPB>>>(rowptr, esrc, enorm, h, b + 0 * D, bufA);
    // layer 1
    k_gemm<true><<<GEMM_BLOCKS, TPB, GEMM_SMEM>>>(bufA, W + 1 * D * D, h);
    k_gather<<<GATH_BLOCKS, TPB>>>(rowptr, esrc, enorm, h, b + 1 * D, bufB);
    // layer 2
    k_gemm<true><<<GEMM_BLOCKS, TPB, GEMM_SMEM>>>(bufB, W + 2 * D * D, h);
    k_gather<<<GATH_BLOCKS, TPB>>>(rowptr, esrc, enorm, h, b + 2 * D, out);
}

// round 5
// speedup vs baseline: 2.7475x; 1.9355x over previous
#include <cuda_runtime.h>
#include <cuda_bf16.h>
#include <cstdint>

#define N_NODES 100000
#define N_EDGES 640000
#define D 128
#define SCAN_BS 1024
#define N_SCAN_BLOCKS ((N_NODES + SCAN_BS - 1) / SCAN_BS)  // 98
#define M_TILE 64
#define GEMM_BLOCKS ((N_NODES + M_TILE - 1) / M_TILE)      // 1563

// ---- scratch (device globals: no allocation allowed) ----
__device__ float g_h[(size_t)N_NODES * D];
__device__ float g_bufA[(size_t)N_NODES * D];
__device__ float g_bufB[(size_t)N_NODES * D];
__device__ int   g_deg[N_NODES];
__device__ float g_dinv[N_NODES];
__device__ int   g_rowptr[N_NODES + 1];
__device__ int   g_cursor[N_NODES];
__device__ int   g_bsum[128];
__device__ int   g_boff[128];
__device__ int   g_esrc[N_EDGES];
__device__ float g_enorm[N_EDGES];
__device__ int   g_ei[2 * N_EDGES];
// W transposed to [n][k], bf16 hi/lo split, pre-XOR-swizzled rows of 256B.
// layout: [layer][hi|lo] each 128 rows x 256B = 32KB -> 3*2*32768
__device__ unsigned char g_wt[3 * 2 * 32768];

// swizzle within a 256B row: XOR byte-offset bits [4:6] with (row&7)<<4
__device__ __forceinline__ uint32_t swz(int row, int kb) {
    return (uint32_t)(row * 256 + (kb ^ ((row & 7) << 4)));
}

__device__ __forceinline__ uint32_t s2u(const void* p) {
    uint32_t a;
    asm("{ .reg .u64 t; cvta.to.shared.u64 t, %1; cvt.u32.u64 %0, t; }"
        : "=r"(a) : "l"(p));
    return a;
}

#define LDSM_X4(d, a) \
    asm volatile("ldmatrix.sync.aligned.m8n8.x4.shared.b16 {%0,%1,%2,%3}, [%4];" \
        : "=r"((d)[0]), "=r"((d)[1]), "=r"((d)[2]), "=r"((d)[3]) : "r"(a))

#define MMA_BF16(c, a, b0, b1) \
    asm volatile("mma.sync.aligned.m16n8k16.row.col.f32.bf16.bf16.f32 " \
        "{%0,%1,%2,%3}, {%4,%5,%6,%7}, {%8,%9}, {%0,%1,%2,%3};" \
        : "+f"((c)[0]), "+f"((c)[1]), "+f"((c)[2]), "+f"((c)[3]) \
        : "r"((a)[0]), "r"((a)[1]), "r"((a)[2]), "r"((a)[3]), "r"(b0), "r"(b1))

// ---------------- edge-index dtype sniff ----------------
__device__ __forceinline__ bool ei_is_int64(const int* __restrict__ w) {
    bool z = true;
#pragma unroll
    for (int i = 1; i < 32; i += 2) z &= (w[i] == 0);
    return z;
}

// fused convert + degree histogram
__global__ void k_convert_hist(const int* __restrict__ ei_raw, int* __restrict__ ei32,
                               int* __restrict__ deg) {
    int e = blockIdx.x * blockDim.x + threadIdx.x;
    if (e >= N_EDGES) return;
    bool is64 = ei_is_int64(ei_raw);
    int r = is64 ? ei_raw[2 * e] : ei_raw[e];
    int c = is64 ? ei_raw[2 * (N_EDGES + e)] : ei_raw[N_EDGES + e];
    ei32[e] = r;
    ei32[N_EDGES + e] = c;
    atomicAdd(&deg[c], 1);
}

// ---------------- W prep: transpose + bf16 hi/lo split + swizzle ----------------
__global__ void k_wprep(const float* __restrict__ W) {
    int i = blockIdx.x * blockDim.x + threadIdx.x;
    if (i >= 3 * 128 * 128) return;
    int l = i >> 14;
    int rem = i & 16383;
    int k = rem >> 7;
    int n = rem & 127;
    float w = W[l * 16384 + k * 128 + n];   // W[l][k][n]
    __nv_bfloat16 hb = __float2bfloat16_rn(w);
    float hf = __bfloat162float(hb);
    __nv_bfloat16 lb = __float2bfloat16_rn(w - hf);
    uint32_t pos = swz(n, k * 2);
    *(__nv_bfloat16*)(g_wt + (size_t)(l * 2 + 0) * 32768 + pos) = hb;
    *(__nv_bfloat16*)(g_wt + (size_t)(l * 2 + 1) * 32768 + pos) = lb;
}

// ---------------- prep: degree / dinv / CSR ----------------
__global__ void k_zeroi(int* __restrict__ p, int n) {
    int i = blockIdx.x * blockDim.x + threadIdx.x;
    if (i < n) p[i] = 0;
}

__global__ void k_dinv(const int* __restrict__ deg, float* __restrict__ dinv) {
    int i = blockIdx.x * blockDim.x + threadIdx.x;
    if (i < N_NODES) {
        int d = deg[i];
        dinv[i] = (d > 0) ? rsqrtf((float)d) : 0.f;
    }
}

__global__ __launch_bounds__(256) void k_blocksum(const int* __restrict__ deg, int* __restrict__ bsum) {
    __shared__ int s[256];
    int b = blockIdx.x, t = threadIdx.x;
    int base = b * SCAN_BS + t * 4;
    int v = 0;
#pragma unroll
    for (int j = 0; j < 4; j++) {
        int i = base + j;
        if (i < N_NODES) v += deg[i];
    }
    s[t] = v;
    __syncthreads();
    for (int off = 128; off > 0; off >>= 1) {
        if (t < off) s[t] += s[t + off];
        __syncthreads();
    }
    if (t == 0) bsum[b] = s[0];
}

__global__ __launch_bounds__(128) void k_scansums(const int* __restrict__ bsum,
                                                  int* __restrict__ boff,
                                                  int* __restrict__ rowptr) {
    __shared__ int s[128];
    int t = threadIdx.x;
    int v = (t < N_SCAN_BLOCKS) ? bsum[t] : 0;
    s[t] = v;
    __syncthreads();
    for (int off = 1; off < 128; off <<= 1) {
        int u = (t >= off) ? s[t - off] : 0;
        __syncthreads();
        s[t] += u;
        __syncthreads();
    }
    if (t < N_SCAN_BLOCKS) boff[t] = s[t] - v;
    if (t == N_SCAN_BLOCKS - 1) rowptr[N_NODES] = s[t];
}

__global__ __launch_bounds__(SCAN_BS) void k_scanapply(const int* __restrict__ deg,
                                                       const int* __restrict__ boff,
                                                       int* __restrict__ rowptr,
                                                       int* __restrict__ cursor) {
    __shared__ int s[SCAN_BS];
    int b = blockIdx.x, t = threadIdx.x;
    int i = b * SCAN_BS + t;
    int v = (i < N_NODES) ? deg[i] : 0;
    s[t] = v;
    __syncthreads();
    for (int off = 1; off < SCAN_BS; off <<= 1) {
        int u = (t >= off) ? s[t - off] : 0;
        __syncthreads();
        s[t] += u;
        __syncthreads();
    }
    if (i < N_NODES) {
        int excl = boff[b] + s[t] - v;
        rowptr[i] = excl;
        cursor[i] = excl;
    }
}

__global__ void k_fill(const int* __restrict__ ei, const float* __restrict__ dinv,
                       int* __restrict__ cursor, int* __restrict__ esrc,
                       float* __restrict__ enorm) {
    int e = blockIdx.x * blockDim.x + threadIdx.x;
    if (e >= N_EDGES) return;
    int r = ei[e];
    int c = ei[N_EDGES + e];
    int pos = atomicAdd(&cursor[c], 1);
    esrc[pos] = r;
    enorm[pos] = dinv[r] * dinv[c];
}

// ---------------- mma.sync GEMM: H = act(X) @ W, 3xBF16 split ----------------
// CTA: 64 rows x 128 cols, 8 warps (2m x 4n), warp tile m32 x n32.
// smem: A_hi 16KB | A_lo 16KB | W_hi 32KB | W_lo 32KB = 96KB (2 CTAs/SM).
#define OFF_AH 0u
#define OFF_AL 16384u
#define OFF_WH 32768u
#define OFF_WL 65536u
#define GEMM_SMEM 98304

__device__ __forceinline__ uint2 pack4(float x, float y, float z, float w) {
    __nv_bfloat162 p0 = __floats2bfloat162_rn(x, y);
    __nv_bfloat162 p1 = __floats2bfloat162_rn(z, w);
    return make_uint2(*(uint32_t*)&p0, *(uint32_t*)&p1);
}

template <bool RELU>
__global__ __launch_bounds__(256, 2) void k_gemm(const float* __restrict__ X,
                                                 int layer,
                                                 float* __restrict__ H) {
    extern __shared__ unsigned char smem[];
    const uint32_t sb = s2u(smem);
    const int tid = threadIdx.x;
    const int w = tid >> 5;
    const int lane = tid & 31;
    const int wm = w >> 2;      // 0..1
    const int wn = w & 3;       // 0..3
    const int row0 = blockIdx.x * M_TILE;

    // ---- stage A: 64 rows x 128, fused act + hi/lo split, swizzled ----
    {
        int r = tid >> 2;        // 0..63
        int q = tid & 3;
        int gr = row0 + r;
        bool valid = gr < N_NODES;
        const float4* src = (const float4*)(X + (size_t)gr * D);
#pragma unroll
        for (int j = 0; j < 8; j++) {
            int qp = q + j * 4;                       // float4 index 0..31
            float4 v = valid ? src[qp] : make_float4(0.f, 0.f, 0.f, 0.f);
            if (RELU) {
                v.x = fmaxf(v.x, 0.f); v.y = fmaxf(v.y, 0.f);
                v.z = fmaxf(v.z, 0.f); v.w = fmaxf(v.w, 0.f);
            }
            uint2 hi = pack4(v.x, v.y, v.z, v.w);
            float hx = __bfloat162float(__float2bfloat16_rn(v.x));
            float hy = __bfloat162float(__float2bfloat16_rn(v.y));
            float hz = __bfloat162float(__float2bfloat16_rn(v.z));
            float hw = __bfloat162float(__float2bfloat16_rn(v.w));
            uint2 lo = pack4(v.x - hx, v.y - hy, v.z - hz, v.w - hw);
            uint32_t addr = swz(r, qp * 8);           // 8 bytes per float4 (as bf16)
            *(uint2*)(smem + OFF_AH + addr) = hi;
            *(uint2*)(smem + OFF_AL + addr) = lo;
        }
    }
    // ---- stage W: copy pre-swizzled hi/lo images (64KB) ----
    {
        const float4* sh = (const float4*)(g_wt + (size_t)(layer * 2 + 0) * 32768);
        const float4* sl = (const float4*)(g_wt + (size_t)(layer * 2 + 1) * 32768);
        float4* dh = (float4*)(smem + OFF_WH);
        float4* dl = (float4*)(smem + OFF_WL);
#pragma unroll
        for (int j = 0; j < 8; j++) {
            dh[tid + j * 256] = sh[tid + j * 256];
            dl[tid + j * 256] = sl[tid + j * 256];
        }
    }
    __syncthreads();

    float acc[2][4][4];
#pragma unroll
    for (int mi = 0; mi < 2; mi++)
#pragma unroll
        for (int ni = 0; ni < 4; ni++)
#pragma unroll
            for (int j = 0; j < 4; j++) acc[mi][ni][j] = 0.f;

    // ldmatrix address components (fixed per thread)
    const int a_row = wm * 32 + (lane & 15);              // + mi*16
    const int a_kb  = (lane >> 4) << 4;                   // + ks*32
    const int b_row = wn * 32 + ((lane >> 4) << 3) + (lane & 7);  // + p*16
    const int b_kb  = ((lane >> 3) & 1) << 4;             // + ks*32

#pragma unroll
    for (int ks = 0; ks < 8; ks++) {
        uint32_t ah[2][4], al[2][4], bh[2][4], bl[2][4];
#pragma unroll
        for (int mi = 0; mi < 2; mi++) {
            uint32_t addr = swz(a_row + mi * 16, a_kb + ks * 32);
            LDSM_X4(ah[mi], sb + OFF_AH + addr);
            LDSM_X4(al[mi], sb + OFF_AL + addr);
        }
#pragma unroll
        for (int p = 0; p < 2; p++) {
            uint32_t addr = swz(b_row + p * 16, b_kb + ks * 32);
            LDSM_X4(bh[p], sb + OFF_WH + addr);
            LDSM_X4(bl[p], sb + OFF_WL + addr);
        }
#pragma unroll
        for (int mi = 0; mi < 2; mi++) {
#pragma unroll
            for (int p = 0; p < 2; p++) {
#pragma unroll
                for (int s = 0; s < 2; s++) {
                    int ni = p * 2 + s;
                    MMA_BF16(acc[mi][ni], ah[mi], bh[p][s * 2], bh[p][s * 2 + 1]);
                    MMA_BF16(acc[mi][ni], ah[mi], bl[p][s * 2], bl[p][s * 2 + 1]);
                    MMA_BF16(acc[mi][ni], al[mi], bh[p][s * 2], bh[p][s * 2 + 1]);
                }
            }
        }
    }

    // ---- epilogue: direct global stores ----
#pragma unroll
    for (int mi = 0; mi < 2; mi++) {
        int r1 = row0 + wm * 32 + mi * 16 + (lane >> 2);
        int r2 = r1 + 8;
#pragma unroll
        for (int ni = 0; ni < 4; ni++) {
            int col = wn * 32 + ni * 8 + 2 * (lane & 3);
            if (r1 < N_NODES)
                *(float2*)(H + (size_t)r1 * D + col) = make_float2(acc[mi][ni][0], acc[mi][ni][1]);
            if (r2 < N_NODES)
                *(float2*)(H + (size_t)r2 * D + col) = make_float2(acc[mi][ni][2], acc[mi][ni][3]);
        }
    }
}

// ---------------- CSR gather: out[n] = b + sum h[esrc]*enorm ----------------
__global__ __launch_bounds__(256) void k_gather(const int* __restrict__ rowptr,
                                                const int* __restrict__ esrc,
                                                const float* __restrict__ enorm,
                                                const float* __restrict__ H,
                                                const float* __restrict__ bvec,
                                                float* __restrict__ out) {
    int n = blockIdx.x * 8 + (threadIdx.x >> 5);
    if (n >= N_NODES) return;
    int lane = threadIdx.x & 31;

    float4 acc = ((const float4*)bvec)[lane];

    int e = rowptr[n];
    int end = rowptr[n + 1];
    for (; e + 4 <= end; e += 4) {
        int s0 = esrc[e], s1 = esrc[e + 1], s2 = esrc[e + 2], s3 = esrc[e + 3];
        float n0 = enorm[e], n1 = enorm[e + 1], n2 = enorm[e + 2], n3 = enorm[e + 3];
        float4 v0 = __ldg(&((const float4*)(H + (size_t)s0 * D))[lane]);
        float4 v1 = __ldg(&((const float4*)(H + (size_t)s1 * D))[lane]);
        float4 v2 = __ldg(&((const float4*)(H + (size_t)s2 * D))[lane]);
        float4 v3 = __ldg(&((const float4*)(H + (size_t)s3 * D))[lane]);
        acc.x += v0.x * n0 + v1.x * n1 + v2.x * n2 + v3.x * n3;
        acc.y += v0.y * n0 + v1.y * n1 + v2.y * n2 + v3.y * n3;
        acc.z += v0.z * n0 + v1.z * n1 + v2.z * n2 + v3.z * n3;
        acc.w += v0.w * n0 + v1.w * n1 + v2.w * n2 + v3.w * n3;
    }
    for (; e < end; e++) {
        int s0 = esrc[e];
        float n0 = enorm[e];
        float4 v0 = __ldg(&((const float4*)(H + (size_t)s0 * D))[lane]);
        acc.x += v0.x * n0; acc.y += v0.y * n0;
        acc.z += v0.z * n0; acc.w += v0.w * n0;
    }
    ((float4*)(out + (size_t)n * D))[lane] = acc;
}

// ---------------- launch ----------------
extern "C" void kernel_launch(void* const* d_in, const int* in_sizes, int n_in,
                              void* d_out, int out_size) {
    const float* x = (const float*)d_in[0];
    const int* ei_raw = (const int*)d_in[1];
    const float* W = (const float*)d_in[3];
    const float* b = (const float*)d_in[4];
    float* out = (float*)d_out;

    float *dinv, *h, *bufA, *bufB, *enorm;
    int *deg, *rowptr, *cursor, *bsum, *boff, *esrc, *ei;
    cudaGetSymbolAddress((void**)&dinv, g_dinv);
    cudaGetSymbolAddress((void**)&h, g_h);
    cudaGetSymbolAddress((void**)&bufA, g_bufA);
    cudaGetSymbolAddress((void**)&bufB, g_bufB);
    cudaGetSymbolAddress((void**)&enorm, g_enorm);
    cudaGetSymbolAddress((void**)&deg, g_deg);
    cudaGetSymbolAddress((void**)&rowptr, g_rowptr);
    cudaGetSymbolAddress((void**)&cursor, g_cursor);
    cudaGetSymbolAddress((void**)&bsum, g_bsum);
    cudaGetSymbolAddress((void**)&boff, g_boff);
    cudaGetSymbolAddress((void**)&esrc, g_esrc);
    cudaGetSymbolAddress((void**)&ei, g_ei);

    cudaFuncSetAttribute(k_gemm<false>, cudaFuncAttributeMaxDynamicSharedMemorySize, GEMM_SMEM);
    cudaFuncSetAttribute(k_gemm<true>, cudaFuncAttributeMaxDynamicSharedMemorySize, GEMM_SMEM);

    const int TPB = 256;
    const int GATH_BLOCKS = (N_NODES + 7) / 8;

    // order keeps the layer-0 GEMM at profiled launch index 3
    k_zeroi<<<(N_NODES + TPB - 1) / TPB, TPB>>>(deg, N_NODES);                    // 0
    k_wprep<<<(3 * 128 * 128 + TPB - 1) / TPB, TPB>>>(W);                         // 1
    k_convert_hist<<<(N_EDGES + TPB - 1) / TPB, TPB>>>(ei_raw, ei, deg);          // 2
    k_gemm<false><<<GEMM_BLOCKS, TPB, GEMM_SMEM>>>(x, 0, h);                      // 3 <- profiled
    k_dinv<<<(N_NODES + TPB - 1) / TPB, TPB>>>(deg, dinv);                        // 4
    k_blocksum<<<N_SCAN_BLOCKS, 256>>>(deg, bsum);                                // 5
    k_scansums<<<1, 128>>>(bsum, boff, rowptr);                                   // 6
    k_scanapply<<<N_SCAN_BLOCKS, SCAN_BS>>>(deg, boff, rowptr, cursor);           // 7
    k_fill<<<(N_EDGES + TPB - 1) / TPB, TPB>>>(ei, dinv, cursor, esrc, enorm);    // 8

    k_gather<<<GATH_BLOCKS, TPB>>>(rowptr, esrc, enorm, h, b + 0 * D, bufA);
    k_gemm<true><<<GEMM_BLOCKS, TPB, GEMM_SMEM>>>(bufA, 1, h);
    k_gather<<<GATH_BLOCKS, TPB>>>(rowptr, esrc, enorm, h, b + 1 * D, bufB);
    k_gemm<true><<<GEMM_BLOCKS, TPB, GEMM_SMEM>>>(bufB, 2, h);
    k_gather<<<GATH_BLOCKS, TPB>>>(rowptr, esrc, enorm, h, b + 2 * D, out);
}

// round 6
// speedup vs baseline: 2.9788x; 1.0842x over previous
#include <cuda_runtime.h>
#include <cuda_bf16.h>
#include <cstdint>

#define N_NODES 100000
#define N_EDGES 640000
#define D 128
#define SCAN_BS 1024
#define N_SCAN_BLOCKS ((N_NODES + SCAN_BS - 1) / SCAN_BS)  // 98
#define M_TILE 64
#define GEMM_BLOCKS ((N_NODES + M_TILE - 1) / M_TILE)      // 1563

// ---- scratch (device globals: no allocation allowed) ----
__device__ float g_h[(size_t)N_NODES * D];
__device__ float g_bufA[(size_t)N_NODES * D];
__device__ float g_bufB[(size_t)N_NODES * D];
__device__ int   g_deg[N_NODES];
__device__ float g_dinv[N_NODES];
__device__ int   g_rowptr[N_NODES + 1];
__device__ int   g_cursor[N_NODES];
__device__ int   g_bsum[128];
__device__ int   g_boff[128];
__device__ int   g_esrc[N_EDGES];
__device__ float g_enorm[N_EDGES];
__device__ int   g_ei[2 * N_EDGES];
// W transposed to [n][k], bf16 hi/lo split, pre-XOR-swizzled rows of 256B.
__device__ unsigned char g_wt[3 * 2 * 32768];

__device__ __forceinline__ uint32_t swz(int row, int kb) {
    return (uint32_t)(row * 256 + (kb ^ ((row & 7) << 4)));
}

__device__ __forceinline__ uint32_t s2u(const void* p) {
    uint32_t a;
    asm("{ .reg .u64 t; cvta.to.shared.u64 t, %1; cvt.u32.u64 %0, t; }"
        : "=r"(a) : "l"(p));
    return a;
}

#define LDSM_X4(d, a) \
    asm volatile("ldmatrix.sync.aligned.m8n8.x4.shared.b16 {%0,%1,%2,%3}, [%4];" \
        : "=r"((d)[0]), "=r"((d)[1]), "=r"((d)[2]), "=r"((d)[3]) : "r"(a))

#define MMA_BF16(c, a, b0, b1) \
    asm volatile("mma.sync.aligned.m16n8k16.row.col.f32.bf16.bf16.f32 " \
        "{%0,%1,%2,%3}, {%4,%5,%6,%7}, {%8,%9}, {%0,%1,%2,%3};" \
        : "+f"((c)[0]), "+f"((c)[1]), "+f"((c)[2]), "+f"((c)[3]) \
        : "r"((a)[0]), "r"((a)[1]), "r"((a)[2]), "r"((a)[3]), "r"(b0), "r"(b1))

#define CP_ASYNC16(dst, src) \
    asm volatile("cp.async.ca.shared.global [%0], [%1], 16;" :: "r"(dst), "l"(src))
#define CP_COMMIT() asm volatile("cp.async.commit_group;")
#define CP_WAIT0()  asm volatile("cp.async.wait_group 0;")

// ---------------- edge-index dtype sniff ----------------
__device__ __forceinline__ bool ei_is_int64(const int* __restrict__ w) {
    bool z = true;
#pragma unroll
    for (int i = 1; i < 32; i += 2) z &= (w[i] == 0);
    return z;
}

__global__ void k_convert_hist(const int* __restrict__ ei_raw, int* __restrict__ ei32,
                               int* __restrict__ deg) {
    int e = blockIdx.x * blockDim.x + threadIdx.x;
    if (e >= N_EDGES) return;
    bool is64 = ei_is_int64(ei_raw);
    int r = is64 ? ei_raw[2 * e] : ei_raw[e];
    int c = is64 ? ei_raw[2 * (N_EDGES + e)] : ei_raw[N_EDGES + e];
    ei32[e] = r;
    ei32[N_EDGES + e] = c;
    atomicAdd(&deg[c], 1);
}

// ---------------- W prep: transpose + bf16 hi/lo split + swizzle ----------------
__global__ void k_wprep(const float* __restrict__ W) {
    int i = blockIdx.x * blockDim.x + threadIdx.x;
    if (i >= 3 * 128 * 128) return;
    int l = i >> 14;
    int rem = i & 16383;
    int k = rem >> 7;
    int n = rem & 127;
    float w = W[l * 16384 + k * 128 + n];
    __nv_bfloat16 hb = __float2bfloat16_rn(w);
    float hf = __bfloat162float(hb);
    __nv_bfloat16 lb = __float2bfloat16_rn(w - hf);
    uint32_t pos = swz(n, k * 2);
    *(__nv_bfloat16*)(g_wt + (size_t)(l * 2 + 0) * 32768 + pos) = hb;
    *(__nv_bfloat16*)(g_wt + (size_t)(l * 2 + 1) * 32768 + pos) = lb;
}

// ---------------- prep ----------------
__global__ void k_zeroi(int* __restrict__ p, int n) {
    int i = blockIdx.x * blockDim.x + threadIdx.x;
    if (i < n) p[i] = 0;
}

// fused: dinv + per-block degree sums
__global__ __launch_bounds__(256) void k_dinv_bsum(const int* __restrict__ deg,
                                                   float* __restrict__ dinv,
                                                   int* __restrict__ bsum) {
    __shared__ int s[256];
    int b = blockIdx.x, t = threadIdx.x;
    int base = b * SCAN_BS + t * 4;
    int v = 0;
#pragma unroll
    for (int j = 0; j < 4; j++) {
        int i = base + j;
        if (i < N_NODES) {
            int d = deg[i];
            dinv[i] = (d > 0) ? rsqrtf((float)d) : 0.f;
            v += d;
        }
    }
    s[t] = v;
    __syncthreads();
    for (int off = 128; off > 0; off >>= 1) {
        if (t < off) s[t] += s[t + off];
        __syncthreads();
    }
    if (t == 0) bsum[b] = s[0];
}

__global__ __launch_bounds__(128) void k_scansums(const int* __restrict__ bsum,
                                                  int* __restrict__ boff,
                                                  int* __restrict__ rowptr) {
    __shared__ int s[128];
    int t = threadIdx.x;
    int v = (t < N_SCAN_BLOCKS) ? bsum[t] : 0;
    s[t] = v;
    __syncthreads();
    for (int off = 1; off < 128; off <<= 1) {
        int u = (t >= off) ? s[t - off] : 0;
        __syncthreads();
        s[t] += u;
        __syncthreads();
    }
    if (t < N_SCAN_BLOCKS) boff[t] = s[t] - v;
    if (t == N_SCAN_BLOCKS - 1) rowptr[N_NODES] = s[t];
}

__global__ __launch_bounds__(SCAN_BS) void k_scanapply(const int* __restrict__ deg,
                                                       const int* __restrict__ boff,
                                                       int* __restrict__ rowptr,
                                                       int* __restrict__ cursor) {
    __shared__ int s[SCAN_BS];
    int b = blockIdx.x, t = threadIdx.x;
    int i = b * SCAN_BS + t;
    int v = (i < N_NODES) ? deg[i] : 0;
    s[t] = v;
    __syncthreads();
    for (int off = 1; off < SCAN_BS; off <<= 1) {
        int u = (t >= off) ? s[t - off] : 0;
        __syncthreads();
        s[t] += u;
        __syncthreads();
    }
    if (i < N_NODES) {
        int excl = boff[b] + s[t] - v;
        rowptr[i] = excl;
        cursor[i] = excl;
    }
}

__global__ void k_fill(const int* __restrict__ ei, const float* __restrict__ dinv,
                       int* __restrict__ cursor, int* __restrict__ esrc,
                       float* __restrict__ enorm) {
    int e = blockIdx.x * blockDim.x + threadIdx.x;
    if (e >= N_EDGES) return;
    int r = ei[e];
    int c = ei[N_EDGES + e];
    int pos = atomicAdd(&cursor[c], 1);
    esrc[pos] = r;
    enorm[pos] = dinv[r] * dinv[c];
}

// ---------------- mma.sync GEMM: H = act(X) @ W, 3xBF16 split ----------------
#define OFF_AH 0u
#define OFF_AL 16384u
#define OFF_WH 32768u
#define OFF_WL 65536u
#define GEMM_SMEM 98304

__device__ __forceinline__ uint2 pack4(float x, float y, float z, float w) {
    __nv_bfloat162 p0 = __floats2bfloat162_rn(x, y);
    __nv_bfloat162 p1 = __floats2bfloat162_rn(z, w);
    return make_uint2(*(uint32_t*)&p0, *(uint32_t*)&p1);
}

template <bool RELU>
__global__ __launch_bounds__(256, 2) void k_gemm(const float* __restrict__ X,
                                                 int layer,
                                                 float* __restrict__ H) {
    extern __shared__ unsigned char smem[];
    const uint32_t sb = s2u(smem);
    const int tid = threadIdx.x;
    const int w = tid >> 5;
    const int lane = tid & 31;
    const int wm = w >> 2;
    const int wn = w & 3;
    const int row0 = blockIdx.x * M_TILE;

    // ---- kick off W copy via cp.async (overlaps with A staging below) ----
    {
        const unsigned char* sh = g_wt + (size_t)(layer * 2 + 0) * 32768;
        const unsigned char* sl = g_wt + (size_t)(layer * 2 + 1) * 32768;
#pragma unroll
        for (int j = 0; j < 8; j++) {
            uint32_t off = (uint32_t)(tid + j * 256) * 16;
            CP_ASYNC16(sb + OFF_WH + off, sh + off);
            CP_ASYNC16(sb + OFF_WL + off, sl + off);
        }
        CP_COMMIT();
    }

    // ---- stage A: 64 rows x 128, fused act + hi/lo split, swizzled ----
    {
        int r = tid >> 2;
        int q = tid & 3;
        int gr = row0 + r;
        bool valid = gr < N_NODES;
        const float4* src = (const float4*)(X + (size_t)gr * D);
#pragma unroll
        for (int j = 0; j < 8; j++) {
            int qp = q + j * 4;
            float4 v = valid ? src[qp] : make_float4(0.f, 0.f, 0.f, 0.f);
            if (RELU) {
                v.x = fmaxf(v.x, 0.f); v.y = fmaxf(v.y, 0.f);
                v.z = fmaxf(v.z, 0.f); v.w = fmaxf(v.w, 0.f);
            }
            uint2 hi = pack4(v.x, v.y, v.z, v.w);
            float hx = __bfloat162float(__float2bfloat16_rn(v.x));
            float hy = __bfloat162float(__float2bfloat16_rn(v.y));
            float hz = __bfloat162float(__float2bfloat16_rn(v.z));
            float hw = __bfloat162float(__float2bfloat16_rn(v.w));
            uint2 lo = pack4(v.x - hx, v.y - hy, v.z - hz, v.w - hw);
            uint32_t addr = swz(r, qp * 8);
            *(uint2*)(smem + OFF_AH + addr) = hi;
            *(uint2*)(smem + OFF_AL + addr) = lo;
        }
    }
    CP_WAIT0();
    __syncthreads();

    float acc[2][4][4];
#pragma unroll
    for (int mi = 0; mi < 2; mi++)
#pragma unroll
        for (int ni = 0; ni < 4; ni++)
#pragma unroll
            for (int j = 0; j < 4; j++) acc[mi][ni][j] = 0.f;

    const int a_row = wm * 32 + (lane & 15);
    const int a_kb  = (lane >> 4) << 4;
    const int b_row = wn * 32 + ((lane >> 4) << 3) + (lane & 7);
    const int b_kb  = ((lane >> 3) & 1) << 4;

#pragma unroll
    for (int ks = 0; ks < 8; ks++) {
        uint32_t ah[2][4], al[2][4], bh[2][4], bl[2][4];
#pragma unroll
        for (int mi = 0; mi < 2; mi++) {
            uint32_t addr = swz(a_row + mi * 16, a_kb + ks * 32);
            LDSM_X4(ah[mi], sb + OFF_AH + addr);
            LDSM_X4(al[mi], sb + OFF_AL + addr);
        }
#pragma unroll
        for (int p = 0; p < 2; p++) {
            uint32_t addr = swz(b_row + p * 16, b_kb + ks * 32);
            LDSM_X4(bh[p], sb + OFF_WH + addr);
            LDSM_X4(bl[p], sb + OFF_WL + addr);
        }
#pragma unroll
        for (int mi = 0; mi < 2; mi++) {
#pragma unroll
            for (int p = 0; p < 2; p++) {
#pragma unroll
                for (int s = 0; s < 2; s++) {
                    int ni = p * 2 + s;
                    MMA_BF16(acc[mi][ni], ah[mi], bh[p][s * 2], bh[p][s * 2 + 1]);
                    MMA_BF16(acc[mi][ni], ah[mi], bl[p][s * 2], bl[p][s * 2 + 1]);
                    MMA_BF16(acc[mi][ni], al[mi], bh[p][s * 2], bh[p][s * 2 + 1]);
                }
            }
        }
    }

#pragma unroll
    for (int mi = 0; mi < 2; mi++) {
        int r1 = row0 + wm * 32 + mi * 16 + (lane >> 2);
        int r2 = r1 + 8;
#pragma unroll
        for (int ni = 0; ni < 4; ni++) {
            int col = wn * 32 + ni * 8 + 2 * (lane & 3);
            if (r1 < N_NODES)
                *(float2*)(H + (size_t)r1 * D + col) = make_float2(acc[mi][ni][0], acc[mi][ni][1]);
            if (r2 < N_NODES)
                *(float2*)(H + (size_t)r2 * D + col) = make_float2(acc[mi][ni][2], acc[mi][ni][3]);
        }
    }
}

// ---------------- CSR gather ----------------
__global__ __launch_bounds__(256) void k_gather(const int* __restrict__ rowptr,
                                                const int* __restrict__ esrc,
                                                const float* __restrict__ enorm,
                                                const float* __restrict__ H,
                                                const float* __restrict__ bvec,
                                                float* __restrict__ out) {
    int n = blockIdx.x * 8 + (threadIdx.x >> 5);
    if (n >= N_NODES) return;
    int lane = threadIdx.x & 31;

    float4 acc = ((const float4*)bvec)[lane];

    int e = rowptr[n];
    int end = rowptr[n + 1];
    for (; e + 4 <= end; e += 4) {
        int s0 = esrc[e], s1 = esrc[e + 1], s2 = esrc[e + 2], s3 = esrc[e + 3];
        float n0 = enorm[e], n1 = enorm[e + 1], n2 = enorm[e + 2], n3 = enorm[e + 3];
        float4 v0 = __ldg(&((const float4*)(H + (size_t)s0 * D))[lane]);
        float4 v1 = __ldg(&((const float4*)(H + (size_t)s1 * D))[lane]);
        float4 v2 = __ldg(&((const float4*)(H + (size_t)s2 * D))[lane]);
        float4 v3 = __ldg(&((const float4*)(H + (size_t)s3 * D))[lane]);
        acc.x += v0.x * n0 + v1.x * n1 + v2.x * n2 + v3.x * n3;
        acc.y += v0.y * n0 + v1.y * n1 + v2.y * n2 + v3.y * n3;
        acc.z += v0.z * n0 + v1.z * n1 + v2.z * n2 + v3.z * n3;
        acc.w += v0.w * n0 + v1.w * n1 + v2.w * n2 + v3.w * n3;
    }
    for (; e < end; e++) {
        int s0 = esrc[e];
        float n0 = enorm[e];
        float4 v0 = __ldg(&((const float4*)(H + (size_t)s0 * D))[lane]);
        acc.x += v0.x * n0; acc.y += v0.y * n0;
        acc.z += v0.z * n0; acc.w += v0.w * n0;
    }
    ((float4*)(out + (size_t)n * D))[lane] = acc;
}

// ---------------- launch ----------------
extern "C" void kernel_launch(void* const* d_in, const int* in_sizes, int n_in,
                              void* d_out, int out_size) {
    const float* x = (const float*)d_in[0];
    const int* ei_raw = (const int*)d_in[1];
    const float* W = (const float*)d_in[3];
    const float* b = (const float*)d_in[4];
    float* out = (float*)d_out;

    float *dinv, *h, *bufA, *bufB, *enorm;
    int *deg, *rowptr, *cursor, *bsum, *boff, *esrc, *ei;
    cudaGetSymbolAddress((void**)&dinv, g_dinv);
    cudaGetSymbolAddress((void**)&h, g_h);
    cudaGetSymbolAddress((void**)&bufA, g_bufA);
    cudaGetSymbolAddress((void**)&bufB, g_bufB);
    cudaGetSymbolAddress((void**)&enorm, g_enorm);
    cudaGetSymbolAddress((void**)&deg, g_deg);
    cudaGetSymbolAddress((void**)&rowptr, g_rowptr);
    cudaGetSymbolAddress((void**)&cursor, g_cursor);
    cudaGetSymbolAddress((void**)&bsum, g_bsum);
    cudaGetSymbolAddress((void**)&boff, g_boff);
    cudaGetSymbolAddress((void**)&esrc, g_esrc);
    cudaGetSymbolAddress((void**)&ei, g_ei);

    cudaFuncSetAttribute(k_gemm<false>, cudaFuncAttributeMaxDynamicSharedMemorySize, GEMM_SMEM);
    cudaFuncSetAttribute(k_gemm<true>, cudaFuncAttributeMaxDynamicSharedMemorySize, GEMM_SMEM);

    const int TPB = 256;
    const int GATH_BLOCKS = (N_NODES + 7) / 8;

    // fork a side stream: wprep + layer-0 GEMM run concurrently with the
    // edge-prep chain (they share no data until gather-0).
    cudaStream_t s2;
    cudaEvent_t evFork, evJoin;
    cudaStreamCreateWithFlags(&s2, cudaStreamNonBlocking);
    cudaEventCreateWithFlags(&evFork, cudaEventDisableTiming);
    cudaEventCreateWithFlags(&evJoin, cudaEventDisableTiming);

    cudaEventRecord(evFork, 0);
    cudaStreamWaitEvent(s2, evFork, 0);

    // side stream: W prep + GEMM layer 0
    k_wprep<<<(3 * 128 * 128 + TPB - 1) / TPB, TPB, 0, s2>>>(W);
    k_gemm<false><<<GEMM_BLOCKS, TPB, GEMM_SMEM, s2>>>(x, 0, h);
    cudaEventRecord(evJoin, s2);

    // main stream: edge prep chain
    k_zeroi<<<(N_NODES + TPB - 1) / TPB, TPB>>>(deg, N_NODES);
    k_convert_hist<<<(N_EDGES + TPB - 1) / TPB, TPB>>>(ei_raw, ei, deg);
    k_dinv_bsum<<<N_SCAN_BLOCKS, 256>>>(deg, dinv, bsum);
    k_scansums<<<1, 128>>>(bsum, boff, rowptr);
    k_scanapply<<<N_SCAN_BLOCKS, SCAN_BS>>>(deg, boff, rowptr, cursor);
    k_fill<<<(N_EDGES + TPB - 1) / TPB, TPB>>>(ei, dinv, cursor, esrc, enorm);

    cudaStreamWaitEvent(0, evJoin, 0);

    // layers (sequential dependency chain)
    k_gather<<<GATH_BLOCKS, TPB>>>(rowptr, esrc, enorm, h, b + 0 * D, bufA);
    k_gemm<true><<<GEMM_BLOCKS, TPB, GEMM_SMEM>>>(bufA, 1, h);
    k_gather<<<GATH_BLOCKS, TPB>>>(rowptr, esrc, enorm, h, b + 1 * D, bufB);
    k_gemm<true><<<GEMM_BLOCKS, TPB, GEMM_SMEM>>>(bufB, 2, h);
    k_gather<<<GATH_BLOCKS, TPB>>>(rowptr, esrc, enorm, h, b + 2 * D, out);
}